// round 13
// baseline (speedup 1.0000x reference)
#include <cuda_runtime.h>
#include <math.h>
#include <math_constants.h>

// Router: logits = x[8192,4096] @ W[4096,64]; per-token top-8 (desc, ties->lower idx);
// softmax over the 8 selected logits.
//
// FROZEN ARITHMETIC (bit-identical to passing R10/R11/R12 kernels):
//   per logit: 13 k-panels (12x320 + 256), ascending; within a panel one plain
//   fp32 FMA chain over ascending k; panel sums folded sequentially with add.rn;
//   topk desc tie->lower-index; softmax = expf(v - top0), fadd_rn chain, fdiv_rn.
//
// R13 schedule changes only:
//   GEMM: TBLK=128 (grid 832 -> 94% wave balance), lane=4-token LDS.128 x-tile,
//         warp=8 experts, double-buffered smem.
//   Fold: 1024 CTAs x 128 threads (8 tokens/CTA), float4 panel folds, warp topk.
//
// Output layout: d_out[0 .. T*8)     = normalized weights (float)
//                d_out[T*8 .. 2*T*8) = selected expert indices (as float)

#define T_TOK 8192
#define D_DIM 4096
#define E_EXP 64
#define TOPK  8
#define KBLK  320                 // Eigen-style k-panel
#define NPAN  13                  // 12*320 + 256 = 4096
#define TBLK  128                 // tokens per GEMM CTA
#define NTB   (T_TOK / TBLK)      // 64
#define KC    16                  // k-tile in shared

// panel partial sums: [panel][tokblock][expert][token-in-block]
__device__ float g_part[NPAN][NTB][E_EXP][TBLK];

__device__ __forceinline__ void ffma2(unsigned long long& acc,
                                      unsigned long long a,
                                      unsigned long long b) {
    asm volatile("fma.rn.f32x2 %0, %1, %2, %0;" : "+l"(acc) : "l"(a), "l"(b));
}
__device__ __forceinline__ float fadd_rn(float a, float b) {
    float r; asm("add.rn.f32 %0, %1, %2;" : "=f"(r) : "f"(a), "f"(b)); return r;
}
__device__ __forceinline__ float fdiv_rn(float a, float b) {
    float r; asm("div.rn.f32 %0, %1, %2;" : "=f"(r) : "f"(a), "f"(b)); return r;
}

__global__ __launch_bounds__(256, 2) void gemm_panel_kernel(
    const float* __restrict__ x,     // [T, D]
    const float* __restrict__ w)     // [D, E]
{
    __shared__ float xs[2][KC][132];   // [buf][k][token], pad 132 (16B-aligned rows, conflict-free)
    __shared__ float wsd[2][KC][132];  // [buf][k][2*expert] duplicated

    const int tid  = threadIdx.x;
    const int wid  = tid >> 5;       // warp -> experts 8*wid .. 8*wid+7
    const int lane = tid & 31;       // lane -> tokens 4*lane .. 4*lane+3 (2 f32x2 pairs)
    const int tok0 = blockIdx.x * TBLK;
    const int p    = blockIdx.y;     // panel index
    const int kbeg = p * KBLK;
    const int ntile = (p == NPAN - 1) ? (D_DIM - (NPAN - 1) * KBLK) / KC : KBLK / KC;

    unsigned long long acc[2][8];    // [token-pair j][expert e]
#pragma unroll
    for (int j = 0; j < 2; j++)
#pragma unroll
        for (int e = 0; e < 8; e++) acc[j][e] = 0ull;

    // x tile load addressing: 2 float4 per thread (128 tok x 16 k)
    const int xtok0 = tid >> 2;            // +64*r
    const int xkq   = tid & 3;
    // w tile load addressing: 1 float4 per thread (16 k x 64 exp)
    const int wr = tid >> 4;
    const int wm = tid & 15;

    float4 xv[2];
    float4 wv;

    // ---- preload tile 0 ----
#pragma unroll
    for (int r = 0; r < 2; r++)
        xv[r] = *reinterpret_cast<const float4*>(
            &x[(size_t)(tok0 + xtok0 + 64 * r) * D_DIM + kbeg + 4 * xkq]);
    wv = *reinterpret_cast<const float4*>(&w[(size_t)(kbeg + wr) * E_EXP + 4 * wm]);
    {
#pragma unroll
        for (int r = 0; r < 2; r++) {
            int tok = xtok0 + 64 * r;
            xs[0][4 * xkq + 0][tok] = xv[r].x;
            xs[0][4 * xkq + 1][tok] = xv[r].y;
            xs[0][4 * xkq + 2][tok] = xv[r].z;
            xs[0][4 * xkq + 3][tok] = xv[r].w;
        }
        wsd[0][wr][8 * wm + 0] = wv.x; wsd[0][wr][8 * wm + 1] = wv.x;
        wsd[0][wr][8 * wm + 2] = wv.y; wsd[0][wr][8 * wm + 3] = wv.y;
        wsd[0][wr][8 * wm + 4] = wv.z; wsd[0][wr][8 * wm + 5] = wv.z;
        wsd[0][wr][8 * wm + 6] = wv.w; wsd[0][wr][8 * wm + 7] = wv.w;
    }
    __syncthreads();

#pragma unroll 1
    for (int t = 0; t < ntile; t++) {
        const int cur = t & 1;
        const bool more = (t + 1) < ntile;

        // prefetch tile t+1 into registers
        if (more) {
            const int k0 = kbeg + (t + 1) * KC;
#pragma unroll
            for (int r = 0; r < 2; r++)
                xv[r] = *reinterpret_cast<const float4*>(
                    &x[(size_t)(tok0 + xtok0 + 64 * r) * D_DIM + k0 + 4 * xkq]);
            wv = *reinterpret_cast<const float4*>(&w[(size_t)(k0 + wr) * E_EXP + 4 * wm]);
        }

        // compute on current buffer
#pragma unroll
        for (int kk = 0; kk < KC; kk++) {
            ulonglong2 q0 = *reinterpret_cast<const ulonglong2*>(&wsd[cur][kk][16 * wid + 0]);
            ulonglong2 q1 = *reinterpret_cast<const ulonglong2*>(&wsd[cur][kk][16 * wid + 4]);
            ulonglong2 q2 = *reinterpret_cast<const ulonglong2*>(&wsd[cur][kk][16 * wid + 8]);
            ulonglong2 q3 = *reinterpret_cast<const ulonglong2*>(&wsd[cur][kk][16 * wid + 12]);
            unsigned long long w2[8] = {q0.x, q0.y, q1.x, q1.y, q2.x, q2.y, q3.x, q3.y};

            ulonglong2 xq = *reinterpret_cast<const ulonglong2*>(&xs[cur][kk][4 * lane]);
            unsigned long long xp[2] = {xq.x, xq.y};

#pragma unroll
            for (int j = 0; j < 2; j++)
#pragma unroll
                for (int e = 0; e < 8; e++)
                    ffma2(acc[j][e], xp[j], w2[e]);
        }

        // stage tile t+1 into the other buffer
        if (more) {
            const int nxt = cur ^ 1;
#pragma unroll
            for (int r = 0; r < 2; r++) {
                int tok = xtok0 + 64 * r;
                xs[nxt][4 * xkq + 0][tok] = xv[r].x;
                xs[nxt][4 * xkq + 1][tok] = xv[r].y;
                xs[nxt][4 * xkq + 2][tok] = xv[r].z;
                xs[nxt][4 * xkq + 3][tok] = xv[r].w;
            }
            wsd[nxt][wr][8 * wm + 0] = wv.x; wsd[nxt][wr][8 * wm + 1] = wv.x;
            wsd[nxt][wr][8 * wm + 2] = wv.y; wsd[nxt][wr][8 * wm + 3] = wv.y;
            wsd[nxt][wr][8 * wm + 4] = wv.z; wsd[nxt][wr][8 * wm + 5] = wv.z;
            wsd[nxt][wr][8 * wm + 6] = wv.w; wsd[nxt][wr][8 * wm + 7] = wv.w;
        }
        __syncthreads();
    }

    // store panel partials (STG.64 per (j,e))
#pragma unroll
    for (int j = 0; j < 2; j++)
#pragma unroll
        for (int e = 0; e < 8; e++)
            *reinterpret_cast<unsigned long long*>(
                &g_part[p][blockIdx.x][8 * wid + e][4 * lane + 2 * j]) = acc[j][e];
}

// ---- fold + topk: 1024 CTAs x 128 threads; 8 tokens per CTA ----
__global__ __launch_bounds__(128) void fold_topk_kernel(float* __restrict__ out)
{
    __shared__ float lgs[8][65];     // [token-in-cta][expert], padded

    const int tid = threadIdx.x;
    const int tb  = blockIdx.x >> 4;            // token block (g_part dim)
    const int t0  = (blockIdx.x & 15) * 8;      // token offset within block

    // fold: thread (e, th) folds 4 tokens of expert e over 13 panels (ascending)
    {
        const int e  = tid & 63;
        const int th = tid >> 6;                // 0..1 -> tokens t0+4*th .. +3
        float s0 = 0.f, s1 = 0.f, s2 = 0.f, s3 = 0.f;
#pragma unroll
        for (int p = 0; p < NPAN; p++) {
            float4 v = *reinterpret_cast<const float4*>(&g_part[p][tb][e][t0 + 4 * th]);
            s0 = fadd_rn(s0, v.x);
            s1 = fadd_rn(s1, v.y);
            s2 = fadd_rn(s2, v.z);
            s3 = fadd_rn(s3, v.w);
        }
        lgs[4 * th + 0][e] = s0;
        lgs[4 * th + 1][e] = s1;
        lgs[4 * th + 2][e] = s2;
        lgs[4 * th + 3][e] = s3;
    }
    __syncthreads();

    // topk + softmax: warp wid handles tokens 2*wid, 2*wid+1 within the CTA
    const int wid  = tid >> 5;
    const int lane = tid & 31;
#pragma unroll 1
    for (int j = 0; j < 2; j++) {
        const int tl = 2 * wid + j;
        float va = lgs[tl][lane];
        float vb = lgs[tl][lane + 32];
        const int ea = lane, eb = lane + 32;

        float topv[TOPK];
        int   topi[TOPK];
#pragma unroll
        for (int s = 0; s < TOPK; s++) {
            float v; int e;
            if (va >= vb) { v = va; e = ea; } else { v = vb; e = eb; }
#pragma unroll
            for (int off = 16; off > 0; off >>= 1) {
                float v2 = __shfl_xor_sync(0xffffffffu, v, off);
                int   e2 = __shfl_xor_sync(0xffffffffu, e, off);
                if (v2 > v || (v2 == v && e2 < e)) { v = v2; e = e2; }
            }
            topv[s] = v;
            topi[s] = e;
            if (ea == e) va = -CUDART_INF_F;
            if (eb == e) vb = -CUDART_INF_F;
        }

        if (lane == 0) {
            const float m = topv[0];
            float ev[TOPK];
            float ssum = 0.f;
#pragma unroll
            for (int q = 0; q < TOPK; q++) { ev[q] = expf(topv[q] - m); ssum = fadd_rn(ssum, ev[q]); }
            const int gtok = tb * TBLK + t0 + tl;
            const size_t base = (size_t)gtok * TOPK;
#pragma unroll
            for (int q = 0; q < TOPK; q++) {
                out[base + q] = fdiv_rn(ev[q], ssum);
                out[(size_t)T_TOK * TOPK + base + q] = (float)topi[q];
            }
        }
    }
}

extern "C" void kernel_launch(void* const* d_in, const int* in_sizes, int n_in,
                              void* d_out, int out_size) {
    const float* x = (const float*)d_in[0];   // [8192, 4096]
    const float* w = (const float*)d_in[1];   // [4096, 64]
    float* out = (float*)d_out;

    gemm_panel_kernel<<<dim3(NTB, NPAN), 256>>>(x, w);
    fold_topk_kernel<<<T_TOK / 8, 128>>>(out);
}